// round 14
// baseline (speedup 1.0000x reference)
#include <cuda_runtime.h>
#include <cuda_fp16.h>

// CapsNet dynamic routing — fused; R9 dataflow at 288 threads / 3 CTAs/SM to
// kill wave-quantization tail (1280 CTAs / 444 slots = 3 rounds vs 5) and
// raise warps/SM 24 -> 27.
// x:  [B=256, N=1152, Ci=8]  fp32
// W:  [C=10, N=1152, Ci=8, Co=16] fp32
// out:[C, B, Co] fp32
//
// Prep: W -> fp16 lane-major, uint4 index (((c*36+g32)*8+i)*2+h)*32+nl.
// Main: 288-thread CTA (9 warps), BT=2, launch_bounds(288,3). Phase 1:
// slot loop (4 x 32 rows/warp, g32 = s*9+wrp), x loaded once per slot,
// inner h loop reuses x; packed fma.rn.f32x2; u stored fp16 h-planes.
// Phase 2: routes b0 then b1, 4 rows/thread packed half2 in registers,
// butterfly shfl reductions, no-max softmax (|logits| << 88).

static constexpr int kB  = 256;
static constexpr int kN  = 1152;
static constexpr int kCi = 8;
static constexpr int kC  = 10;
static constexpr int kCo = 16;
static constexpr int kBT = 2;
static constexpr int kThreads = 288;   // 9 warps
static constexpr int kWarps = 9;
static constexpr int kRows = 4;        // 1152 / 288
static constexpr int kSlots = 4;       // phase-1 row slots (288 rows each)

static constexpr int kWTotal = kC * kN * kCi * kCo;   // halfs

__device__ __half g_Wt[kWTotal];

struct Smem {
    uint4 u[kBT][2][kN];        // fp16 priors: [b][h][n] -> 8 halfs (co = 8h+j)
    float red[kWarps][kCo];
    float zsc[kWarps];
    float vv[kCo];
};

// ---------------- packed f32x2 helpers --------------------------------------
__device__ __forceinline__ unsigned long long pk2(float a, float b) {
    unsigned long long r;
    asm("mov.b64 %0, {%1, %2};" : "=l"(r) : "f"(a), "f"(b));
    return r;
}
__device__ __forceinline__ unsigned long long fma2(unsigned long long a,
                                                   unsigned long long b,
                                                   unsigned long long c) {
    unsigned long long d;
    asm("fma.rn.f32x2 %0, %1, %2, %3;" : "=l"(d) : "l"(a), "l"(b), "l"(c));
    return d;
}
__device__ __forceinline__ float2 upk2(unsigned long long a) {
    float x, y;
    asm("mov.b64 {%0, %1}, %2;" : "=f"(x), "=f"(y) : "l"(a));
    return make_float2(x, y);
}

// ---------------- prep: coalesced SMEM-transpose + fp16 convert -------------
__global__ __launch_bounds__(256)
void transpose_W_kernel(const float* __restrict__ W) {
    __shared__ __half s[32][136];          // 128 halfs/row + 8 pad
    const int blk = blockIdx.x;            // c*36 + g32
    const int tid = threadIdx.x;

    const float4* src = reinterpret_cast<const float4*>(W) + (size_t)blk * 1024;
    #pragma unroll
    for (int q = 0; q < 4; ++q) {
        const int v  = tid + q * 256;
        float4 f = src[v];
        const int nl  = v >> 5;
        const int col = (v & 31) * 4;
        *reinterpret_cast<__half2*>(&s[nl][col])     = __floats2half2_rn(f.x, f.y);
        *reinterpret_cast<__half2*>(&s[nl][col + 2]) = __floats2half2_rn(f.z, f.w);
    }
    __syncthreads();

    uint4* dst = reinterpret_cast<uint4*>(g_Wt) + (size_t)blk * 512;
    #pragma unroll
    for (int q = 0; q < 2; ++q) {
        const int o  = tid + q * 256;
        const int nl = o & 31;
        const int ih = o >> 5;             // i*2 + h
        dst[o] = *reinterpret_cast<const uint4*>(&s[nl][ih * 8]);
    }
}

// ---------------- helpers ----------------------------------------------------
__device__ __forceinline__ float warp_reduce16(float a[kCo], int lane) {
    #pragma unroll
    for (int b = 0; b < 4; ++b) {
        const int off = 1 << b;
        const bool hi = (lane >> b) & 1;
        const int hh = 16 >> (b + 1);
        #pragma unroll
        for (int i = 0; i < hh; ++i) {
            float send = hi ? a[i] : a[i + hh];
            float recv = __shfl_xor_sync(0xFFFFFFFFu, send, off);
            a[i] = (hi ? a[i + hh] : a[i]) + recv;
        }
    }
    return a[0] + __shfl_xor_sync(0xFFFFFFFFu, a[0], 16);
}

__device__ __forceinline__ int bitrev4(int l) {
    return ((l & 1) << 3) | ((l & 2) << 1) | ((l & 4) >> 1) | ((l & 8) >> 3);
}

// Routing for one b on register-resident packed u (R9 scheme, kRows=4).
__device__ __forceinline__ void route_one(
    Smem& sm, const __half2 u2[kRows][8],
    int tid, int lane, int wrp, int corev,
    float* __restrict__ outp)
{
    float lg[kRows];

    // ---- iteration 0: uniform probs ----
    {
        float r[kCo];
        #pragma unroll
        for (int j = 0; j < 8; ++j) {
            float2 f0 = __half22float2(u2[0][j]);
            float2 f1 = __half22float2(u2[1][j]);
            float2 f2 = __half22float2(u2[2][j]);
            float2 f3 = __half22float2(u2[3][j]);
            r[2*j]   = (f0.x + f1.x) + (f2.x + f3.x);
            r[2*j+1] = (f0.y + f1.y) + (f2.y + f3.y);
        }
        float tot = warp_reduce16(r, lane);
        if (lane < 16) sm.red[wrp][corev] = tot;
        __syncthreads();

        if (tid < kCo) {
            float s = 0.f;
            #pragma unroll
            for (int w = 0; w < kWarps; ++w) s += sm.red[w][tid];
            s *= (1.0f / kN);
            float sq = s * s;
            #pragma unroll
            for (int off = 8; off; off >>= 1)
                sq += __shfl_xor_sync(0x0000FFFFu, sq, off);
            sm.vv[tid] = s * sqrtf(sq) / (1.0f + sq);
        }
        __syncthreads();

        float v[kCo];
        #pragma unroll
        for (int co = 0; co < kCo; ++co) v[co] = sm.vv[co];
        #pragma unroll
        for (int k = 0; k < kRows; ++k) {
            float d = 0.f;
            #pragma unroll
            for (int j = 0; j < 8; ++j) {
                float2 f = __half22float2(u2[k][j]);
                d += f.x * v[2*j] + f.y * v[2*j+1];
            }
            lg[k] = d;
        }
    }

    // ---- iterations 1, 2 (no-max softmax: |logits| << 88) ----
    #pragma unroll 1
    for (int it = 1; it < 3; ++it) {
        float e[kRows];
        float zp = 0.f;
        #pragma unroll
        for (int k = 0; k < kRows; ++k) {
            e[k] = __expf(lg[k]);
            zp += e[k];
        }
        #pragma unroll
        for (int off = 16; off; off >>= 1)
            zp += __shfl_xor_sync(0xFFFFFFFFu, zp, off);

        float r[kCo];
        #pragma unroll
        for (int j = 0; j < 8; ++j) {
            float2 f0 = __half22float2(u2[0][j]);
            float2 f1 = __half22float2(u2[1][j]);
            float2 f2 = __half22float2(u2[2][j]);
            float2 f3 = __half22float2(u2[3][j]);
            r[2*j]   = (e[0]*f0.x + e[1]*f1.x) + (e[2]*f2.x + e[3]*f3.x);
            r[2*j+1] = (e[0]*f0.y + e[1]*f1.y) + (e[2]*f2.y + e[3]*f3.y);
        }
        float tot = warp_reduce16(r, lane);
        if (lane == 0) sm.zsc[wrp] = zp;
        if (lane < 16) sm.red[wrp][corev] = tot;
        __syncthreads();

        if (tid < kCo) {
            float Z = 0.f, s = 0.f;
            #pragma unroll
            for (int w = 0; w < kWarps; ++w) { Z += sm.zsc[w]; s += sm.red[w][tid]; }
            s = __fdividef(s, Z);
            float sq = s * s;
            #pragma unroll
            for (int off = 8; off; off >>= 1)
                sq += __shfl_xor_sync(0x0000FFFFu, sq, off);
            float v = s * sqrtf(sq) / (1.0f + sq);
            sm.vv[tid] = v;
            if (it == 2)
                outp[tid] = v;
        }
        __syncthreads();

        if (it == 1) {
            float v[kCo];
            #pragma unroll
            for (int co = 0; co < kCo; ++co) v[co] = sm.vv[co];
            #pragma unroll
            for (int k = 0; k < kRows; ++k) {
                float d = 0.f;
                #pragma unroll
                for (int j = 0; j < 8; ++j) {
                    float2 f = __half22float2(u2[k][j]);
                    d += f.x * v[2*j] + f.y * v[2*j+1];
                }
                lg[k] += d;
            }
        }
    }
}

// ---------------- main --------------------------------------------------------
__global__ __launch_bounds__(kThreads, 3)
void caps_routing_kernel(const float* __restrict__ x,
                         float* __restrict__ out)
{
    extern __shared__ unsigned char smem_u8[];
    Smem& sm = *reinterpret_cast<Smem*>(smem_u8);

    const int tid  = threadIdx.x;
    const int lane = tid & 31;
    const int wrp  = tid >> 5;           // 0..8
    const int c    = blockIdx.y;
    const int b0   = blockIdx.x * kBT;
    const int corev = bitrev4(lane & 15);

    // ---------------- Phase 1: priors -> fp16 SMEM planes ------------------
    // slot loop: warp covers 32 consecutive rows; x loaded once per slot,
    // inner h loop reuses it.
    {
        const float4* __restrict__ X4  = reinterpret_cast<const float4*>(x);
        const uint4*  __restrict__ Wt4 = reinterpret_cast<const uint4*>(g_Wt);

        #pragma unroll 1
        for (int s = 0; s < kSlots; ++s) {
            const int n   = s * 288 + wrp * 32 + lane;
            const int g32 = s * 9 + wrp;              // == n >> 5

            float4 xa0 = X4[(b0 * kN + n) * 2 + 0];
            float4 xb0 = X4[(b0 * kN + n) * 2 + 1];
            float4 xa1 = X4[((b0 + 1) * kN + n) * 2 + 0];
            float4 xb1 = X4[((b0 + 1) * kN + n) * 2 + 1];
            float x0v[8] = {xa0.x, xa0.y, xa0.z, xa0.w, xb0.x, xb0.y, xb0.z, xb0.w};
            float x1v[8] = {xa1.x, xa1.y, xa1.z, xa1.w, xb1.x, xb1.y, xb1.z, xb1.w};

            #pragma unroll
            for (int h = 0; h < 2; ++h) {
                unsigned long long acc0[4] = {0ull, 0ull, 0ull, 0ull};
                unsigned long long acc1[4] = {0ull, 0ull, 0ull, 0ull};
                const size_t wb = ((size_t)(c * 36 + g32) * 16 + h) * 32 + lane;
                #pragma unroll
                for (int i = 0; i < kCi; ++i) {
                    uint4 w = Wt4[wb + (size_t)i * 64];
                    const __half2* hp = reinterpret_cast<const __half2*>(&w);
                    const unsigned long long xi0 = pk2(x0v[i], x0v[i]);
                    const unsigned long long xi1 = pk2(x1v[i], x1v[i]);
                    #pragma unroll
                    for (int q = 0; q < 4; ++q) {
                        float2 f = __half22float2(hp[q]);
                        unsigned long long wp = pk2(f.x, f.y);
                        acc0[q] = fma2(xi0, wp, acc0[q]);
                        acc1[q] = fma2(xi1, wp, acc1[q]);
                    }
                }
                __half2 p0[4], p1[4];
                #pragma unroll
                for (int q = 0; q < 4; ++q) {
                    float2 f0 = upk2(acc0[q]);
                    float2 f1 = upk2(acc1[q]);
                    p0[q] = __floats2half2_rn(f0.x, f0.y);
                    p1[q] = __floats2half2_rn(f1.x, f1.y);
                }
                sm.u[0][h][n] = *reinterpret_cast<uint4*>(p0);
                sm.u[1][h][n] = *reinterpret_cast<uint4*>(p1);
            }
        }
    }
    __syncthreads();

    // ---------------- Phase 2: routing, sequential over b ------------------
    #pragma unroll 1
    for (int bb = 0; bb < kBT; ++bb) {
        __half2 u2[kRows][8];
        #pragma unroll
        for (int k = 0; k < kRows; ++k) {
            const int n = tid + k * kThreads;
            uint4 lo = sm.u[bb][0][n];
            uint4 hi = sm.u[bb][1][n];
            const __half2* l2 = reinterpret_cast<const __half2*>(&lo);
            const __half2* h2 = reinterpret_cast<const __half2*>(&hi);
            #pragma unroll
            for (int q = 0; q < 4; ++q) { u2[k][q] = l2[q]; u2[k][4+q] = h2[q]; }
        }

        route_one(sm, u2, tid, lane, wrp, corev,
                  out + (c * kB + b0 + bb) * kCo);
    }
}

extern "C" void kernel_launch(void* const* d_in, const int* in_sizes, int n_in,
                              void* d_out, int out_size)
{
    const float* x = (const float*)d_in[0];
    const float* W = (const float*)d_in[1];
    float* out = (float*)d_out;

    transpose_W_kernel<<<kC * 36, 256>>>(W);

    cudaFuncSetAttribute(caps_routing_kernel,
                         cudaFuncAttributeMaxDynamicSharedMemorySize,
                         (int)sizeof(Smem));
    dim3 grid(kB / kBT, kC);
    caps_routing_kernel<<<grid, kThreads, sizeof(Smem)>>>(x, out);
}

// round 15
// speedup vs baseline: 1.1421x; 1.1421x over previous
#include <cuda_runtime.h>
#include <cuda_fp16.h>

// CapsNet dynamic routing — fused, 2 CTAs/SM. R9 (champion) with one change:
// slot-loop phase 1 that loads each x row ONCE and reuses it for both co-octs
// (h=0,1), removing 1152 redundant x wavefronts and 12 LDGs/thread per block.
// x:  [B=256, N=1152, Ci=8]  fp32
// W:  [C=10, N=1152, Ci=8, Co=16] fp32
// out:[C, B, Co] fp32
//
// Prep: W -> fp16 lane-major, uint4 index (((c*36+g32)*8+i)*2+h)*32+nl.
// Main: 384-thread CTA (12 warps), BT=2, launch_bounds(384,2). Phase 1:
// 3 slots x (warp owns 32 consecutive rows); x loaded once per slot, inner
// h loop reuses it; packed fma.rn.f32x2; u stored fp16 h-planes per b.
// Phase 2: routes b0 then b1, 3 rows/thread packed half2 in registers,
// butterfly shfl reductions, no-max softmax (|logits| << 88).

static constexpr int kB  = 256;
static constexpr int kN  = 1152;
static constexpr int kCi = 8;
static constexpr int kC  = 10;
static constexpr int kCo = 16;
static constexpr int kBT = 2;
static constexpr int kThreads = 384;   // 12 warps
static constexpr int kWarps = 12;
static constexpr int kRows = 3;        // 1152 / 384 (phase-2 rows/thread)
static constexpr int kSlots = 3;       // phase-1 slots (384 rows each)

static constexpr int kWTotal = kC * kN * kCi * kCo;   // halfs

__device__ __half g_Wt[kWTotal];

struct Smem {
    uint4 u[kBT][2][kN];        // fp16 priors: [b][h][n] -> 8 halfs (co = 8h+j)
    float red[kWarps][kCo];
    float zsc[kWarps];
    float vv[kCo];
};

// ---------------- packed f32x2 helpers --------------------------------------
__device__ __forceinline__ unsigned long long pk2(float a, float b) {
    unsigned long long r;
    asm("mov.b64 %0, {%1, %2};" : "=l"(r) : "f"(a), "f"(b));
    return r;
}
__device__ __forceinline__ unsigned long long fma2(unsigned long long a,
                                                   unsigned long long b,
                                                   unsigned long long c) {
    unsigned long long d;
    asm("fma.rn.f32x2 %0, %1, %2, %3;" : "=l"(d) : "l"(a), "l"(b), "l"(c));
    return d;
}
__device__ __forceinline__ float2 upk2(unsigned long long a) {
    float x, y;
    asm("mov.b64 {%0, %1}, %2;" : "=f"(x), "=f"(y) : "l"(a));
    return make_float2(x, y);
}

// ---------------- prep: coalesced SMEM-transpose + fp16 convert -------------
__global__ __launch_bounds__(256)
void transpose_W_kernel(const float* __restrict__ W) {
    __shared__ __half s[32][136];          // 128 halfs/row + 8 pad
    const int blk = blockIdx.x;            // c*36 + g32
    const int tid = threadIdx.x;

    const float4* src = reinterpret_cast<const float4*>(W) + (size_t)blk * 1024;
    #pragma unroll
    for (int q = 0; q < 4; ++q) {
        const int v  = tid + q * 256;
        float4 f = src[v];
        const int nl  = v >> 5;
        const int col = (v & 31) * 4;
        *reinterpret_cast<__half2*>(&s[nl][col])     = __floats2half2_rn(f.x, f.y);
        *reinterpret_cast<__half2*>(&s[nl][col + 2]) = __floats2half2_rn(f.z, f.w);
    }
    __syncthreads();

    uint4* dst = reinterpret_cast<uint4*>(g_Wt) + (size_t)blk * 512;
    #pragma unroll
    for (int q = 0; q < 2; ++q) {
        const int o  = tid + q * 256;
        const int nl = o & 31;
        const int ih = o >> 5;             // i*2 + h
        dst[o] = *reinterpret_cast<const uint4*>(&s[nl][ih * 8]);
    }
}

// ---------------- helpers ----------------------------------------------------
__device__ __forceinline__ float warp_reduce16(float a[kCo], int lane) {
    #pragma unroll
    for (int b = 0; b < 4; ++b) {
        const int off = 1 << b;
        const bool hi = (lane >> b) & 1;
        const int hh = 16 >> (b + 1);
        #pragma unroll
        for (int i = 0; i < hh; ++i) {
            float send = hi ? a[i] : a[i + hh];
            float recv = __shfl_xor_sync(0xFFFFFFFFu, send, off);
            a[i] = (hi ? a[i + hh] : a[i]) + recv;
        }
    }
    return a[0] + __shfl_xor_sync(0xFFFFFFFFu, a[0], 16);
}

__device__ __forceinline__ int bitrev4(int l) {
    return ((l & 1) << 3) | ((l & 2) << 1) | ((l & 4) >> 1) | ((l & 8) >> 3);
}

// Routing for one b on register-resident packed u (R9 scheme).
__device__ __forceinline__ void route_one(
    Smem& sm, const __half2 u2[kRows][8],
    int tid, int lane, int wrp, int corev,
    float* __restrict__ outp)
{
    float lg[kRows];

    // ---- iteration 0: uniform probs ----
    {
        float r[kCo];
        #pragma unroll
        for (int j = 0; j < 8; ++j) {
            float2 f0 = __half22float2(u2[0][j]);
            float2 f1 = __half22float2(u2[1][j]);
            float2 f2 = __half22float2(u2[2][j]);
            r[2*j]   = f0.x + f1.x + f2.x;
            r[2*j+1] = f0.y + f1.y + f2.y;
        }
        float tot = warp_reduce16(r, lane);
        if (lane < 16) sm.red[wrp][corev] = tot;
        __syncthreads();

        if (tid < kCo) {
            float s = 0.f;
            #pragma unroll
            for (int w = 0; w < kWarps; ++w) s += sm.red[w][tid];
            s *= (1.0f / kN);
            float sq = s * s;
            #pragma unroll
            for (int off = 8; off; off >>= 1)
                sq += __shfl_xor_sync(0x0000FFFFu, sq, off);
            sm.vv[tid] = s * sqrtf(sq) / (1.0f + sq);
        }
        __syncthreads();

        float v[kCo];
        #pragma unroll
        for (int co = 0; co < kCo; ++co) v[co] = sm.vv[co];
        #pragma unroll
        for (int k = 0; k < kRows; ++k) {
            float d = 0.f;
            #pragma unroll
            for (int j = 0; j < 8; ++j) {
                float2 f = __half22float2(u2[k][j]);
                d += f.x * v[2*j] + f.y * v[2*j+1];
            }
            lg[k] = d;
        }
    }

    // ---- iterations 1, 2 (no-max softmax: |logits| << 88) ----
    #pragma unroll 1
    for (int it = 1; it < 3; ++it) {
        float e[kRows];
        float zp = 0.f;
        #pragma unroll
        for (int k = 0; k < kRows; ++k) {
            e[k] = __expf(lg[k]);
            zp += e[k];
        }
        #pragma unroll
        for (int off = 16; off; off >>= 1)
            zp += __shfl_xor_sync(0xFFFFFFFFu, zp, off);

        float r[kCo];
        #pragma unroll
        for (int j = 0; j < 8; ++j) {
            float2 f0 = __half22float2(u2[0][j]);
            float2 f1 = __half22float2(u2[1][j]);
            float2 f2 = __half22float2(u2[2][j]);
            r[2*j]   = e[0]*f0.x + e[1]*f1.x + e[2]*f2.x;
            r[2*j+1] = e[0]*f0.y + e[1]*f1.y + e[2]*f2.y;
        }
        float tot = warp_reduce16(r, lane);
        if (lane == 0) sm.zsc[wrp] = zp;
        if (lane < 16) sm.red[wrp][corev] = tot;
        __syncthreads();

        if (tid < kCo) {
            float Z = 0.f, s = 0.f;
            #pragma unroll
            for (int w = 0; w < kWarps; ++w) { Z += sm.zsc[w]; s += sm.red[w][tid]; }
            s = __fdividef(s, Z);
            float sq = s * s;
            #pragma unroll
            for (int off = 8; off; off >>= 1)
                sq += __shfl_xor_sync(0x0000FFFFu, sq, off);
            float v = s * sqrtf(sq) / (1.0f + sq);
            sm.vv[tid] = v;
            if (it == 2)
                outp[tid] = v;
        }
        __syncthreads();

        if (it == 1) {
            float v[kCo];
            #pragma unroll
            for (int co = 0; co < kCo; ++co) v[co] = sm.vv[co];
            #pragma unroll
            for (int k = 0; k < kRows; ++k) {
                float d = 0.f;
                #pragma unroll
                for (int j = 0; j < 8; ++j) {
                    float2 f = __half22float2(u2[k][j]);
                    d += f.x * v[2*j] + f.y * v[2*j+1];
                }
                lg[k] += d;
            }
        }
    }
}

// ---------------- main --------------------------------------------------------
__global__ __launch_bounds__(kThreads, 2)
void caps_routing_kernel(const float* __restrict__ x,
                         float* __restrict__ out)
{
    extern __shared__ unsigned char smem_u8[];
    Smem& sm = *reinterpret_cast<Smem*>(smem_u8);

    const int tid  = threadIdx.x;
    const int lane = tid & 31;
    const int wrp  = tid >> 5;           // 0..11
    const int c    = blockIdx.y;
    const int b0   = blockIdx.x * kBT;
    const int corev = bitrev4(lane & 15);

    // ---------------- Phase 1: priors -> fp16 SMEM planes ------------------
    // 3 slots; warp owns 32 consecutive rows per slot. x loaded ONCE per
    // slot and reused for both h (co-oct) passes.
    {
        const float4* __restrict__ X4  = reinterpret_cast<const float4*>(x);
        const uint4*  __restrict__ Wt4 = reinterpret_cast<const uint4*>(g_Wt);

        #pragma unroll 1
        for (int s = 0; s < kSlots; ++s) {
            const int n   = s * 384 + wrp * 32 + lane;
            const int g32 = s * 12 + wrp;             // == n >> 5

            float4 xa0 = X4[(b0 * kN + n) * 2 + 0];
            float4 xb0 = X4[(b0 * kN + n) * 2 + 1];
            float4 xa1 = X4[((b0 + 1) * kN + n) * 2 + 0];
            float4 xb1 = X4[((b0 + 1) * kN + n) * 2 + 1];
            float x0v[8] = {xa0.x, xa0.y, xa0.z, xa0.w, xb0.x, xb0.y, xb0.z, xb0.w};
            float x1v[8] = {xa1.x, xa1.y, xa1.z, xa1.w, xb1.x, xb1.y, xb1.z, xb1.w};

            #pragma unroll
            for (int h = 0; h < 2; ++h) {
                unsigned long long acc0[4] = {0ull, 0ull, 0ull, 0ull};
                unsigned long long acc1[4] = {0ull, 0ull, 0ull, 0ull};
                const size_t wb = ((size_t)(c * 36 + g32) * 16 + h) * 32 + lane;
                #pragma unroll
                for (int i = 0; i < kCi; ++i) {
                    uint4 w = Wt4[wb + (size_t)i * 64];
                    const __half2* hp = reinterpret_cast<const __half2*>(&w);
                    const unsigned long long xi0 = pk2(x0v[i], x0v[i]);
                    const unsigned long long xi1 = pk2(x1v[i], x1v[i]);
                    #pragma unroll
                    for (int q = 0; q < 4; ++q) {
                        float2 f = __half22float2(hp[q]);
                        unsigned long long wp = pk2(f.x, f.y);
                        acc0[q] = fma2(xi0, wp, acc0[q]);
                        acc1[q] = fma2(xi1, wp, acc1[q]);
                    }
                }
                __half2 p0[4], p1[4];
                #pragma unroll
                for (int q = 0; q < 4; ++q) {
                    float2 f0 = upk2(acc0[q]);
                    float2 f1 = upk2(acc1[q]);
                    p0[q] = __floats2half2_rn(f0.x, f0.y);
                    p1[q] = __floats2half2_rn(f1.x, f1.y);
                }
                sm.u[0][h][n] = *reinterpret_cast<uint4*>(p0);
                sm.u[1][h][n] = *reinterpret_cast<uint4*>(p1);
            }
        }
    }
    __syncthreads();

    // ---------------- Phase 2: routing, sequential over b ------------------
    #pragma unroll 1
    for (int bb = 0; bb < kBT; ++bb) {
        __half2 u2[kRows][8];
        #pragma unroll
        for (int k = 0; k < kRows; ++k) {
            const int n = tid + k * kThreads;
            uint4 lo = sm.u[bb][0][n];
            uint4 hi = sm.u[bb][1][n];
            const __half2* l2 = reinterpret_cast<const __half2*>(&lo);
            const __half2* h2 = reinterpret_cast<const __half2*>(&hi);
            #pragma unroll
            for (int q = 0; q < 4; ++q) { u2[k][q] = l2[q]; u2[k][4+q] = h2[q]; }
        }

        route_one(sm, u2, tid, lane, wrp, corev,
                  out + (c * kB + b0 + bb) * kCo);
    }
}

extern "C" void kernel_launch(void* const* d_in, const int* in_sizes, int n_in,
                              void* d_out, int out_size)
{
    const float* x = (const float*)d_in[0];
    const float* W = (const float*)d_in[1];
    float* out = (float*)d_out;

    transpose_W_kernel<<<kC * 36, 256>>>(W);

    cudaFuncSetAttribute(caps_routing_kernel,
                         cudaFuncAttributeMaxDynamicSharedMemorySize,
                         (int)sizeof(Smem));
    dim3 grid(kB / kBT, kC);
    caps_routing_kernel<<<grid, kThreads, sizeof(Smem)>>>(x, out);
}